// round 12
// baseline (speedup 1.0000x reference)
#include <cuda_runtime.h>

// ---------------------------------------------------------------------------
// Shapes: b=4, h=8, l=1024, d=64. Per-batch flat matrix M: 1024 x 512.
// Outputs: context (4,8,1024,64) then attn_out (4,8,4,1024).
// ---------------------------------------------------------------------------

__device__ float  g_cre[2 * 4 * 1024 * 512];
__device__ float  g_cim[2 * 4 * 1024 * 512];
__device__ float  g_Mq [4 * 1024 * 512];
__device__ float  g_Mk [4 * 1024 * 512];
// P layout: [bh(32)][p(4)][d(64)][l(1024)]
__device__ float  g_Pq [32 * 4 * 64 * 1024];
__device__ float  g_Pk [32 * 4 * 64 * 1024];

// ----------------------------- f32x2 helpers -------------------------------
__device__ __forceinline__ unsigned long long pk2(float a, float b) {
    unsigned long long r;
    asm("mov.b64 %0, {%1, %2};" : "=l"(r) : "f"(a), "f"(b));
    return r;
}
__device__ __forceinline__ unsigned long long ffma2(unsigned long long a,
                                                    unsigned long long b,
                                                    unsigned long long c) {
    unsigned long long d;
    asm("fma.rn.f32x2 %0, %1, %2, %3;" : "=l"(d) : "l"(a), "l"(b), "l"(c));
    return d;
}

// ---------------------------------------------------------------------------
// Stage 1: 512-pt FFT along each contiguous row. Handles Q and K in one grid.
// ---------------------------------------------------------------------------
__global__ void fft512_rows(const float* __restrict__ Qin,
                            const float* __restrict__ Kin) {
    __shared__ float re[512], im[512];
    int R = blockIdx.x;                        // 0..8191
    const float* src = (R < 4096) ? Qin : Kin;
    const float* row = src + (size_t)(R & 4095) * 512;
    int t = threadIdx.x;  // 256
    for (int i = t; i < 512; i += 256) {
        re[i] = row[__brev((unsigned)i) >> 23];
        im[i] = 0.f;
    }
    __syncthreads();
    for (int s = 0; s < 9; s++) {
        int hl = 1 << s;
        int pos = t & (hl - 1);
        int i0 = ((t >> s) << (s + 1)) + pos;
        int i1 = i0 + hl;
        float si, co;
        sincospif(-(float)pos / (float)hl, &si, &co);
        float xr = re[i1], xi = im[i1];
        float tr = co * xr - si * xi;
        float ti = co * xi + si * xr;
        float ur = re[i0], ui = im[i0];
        re[i0] = ur + tr; im[i0] = ui + ti;
        re[i1] = ur - tr; im[i1] = ui - ti;
        __syncthreads();
    }
    float* cr = g_cre + (size_t)R * 512;
    float* ci = g_cim + (size_t)R * 512;
    for (int i = t; i < 512; i += 256) { cr[i] = re[i]; ci[i] = im[i]; }
}

// ---------------------------------------------------------------------------
// Stage 2: 1024-pt FFT along columns, keep real part. Handles Q and K.
// ---------------------------------------------------------------------------
__global__ void fft1024_cols() {
    __shared__ float re[4096], im[4096];
    int t = threadIdx.x;                 // 512
    int bi2 = blockIdx.x >> 7;           // 0..7 = which*4 + b
    int j0  = (blockIdx.x & 127) << 2;
    size_t gb = (size_t)bi2 << 19;
    for (int idx = t; idx < 4096; idx += 512) {
        int r = idx >> 2, c = idx & 3;
        int rv = __brev((unsigned)r) >> 22;
        size_t a = gb + (size_t)rv * 512 + j0 + c;
        re[idx] = g_cre[a];
        im[idx] = g_cim[a];
    }
    __syncthreads();
    for (int s = 0; s < 10; s++) {
        for (int u = t; u < 2048; u += 512) {
            int c = u & 3, jb = u >> 2;
            int hl = 1 << s;
            int pos = jb & (hl - 1);
            int i0 = ((jb >> s) << (s + 1)) + pos;
            int i1 = i0 + hl;
            float si, co;
            sincospif(-(float)pos / (float)hl, &si, &co);
            int a0 = (i0 << 2) + c, a1 = (i1 << 2) + c;
            float xr = re[a1], xi = im[a1];
            float tr = co * xr - si * xi;
            float ti = co * xi + si * xr;
            float ur = re[a0], ui = im[a0];
            re[a0] = ur + tr; im[a0] = ui + ti;
            re[a1] = ur - tr; im[a1] = ui - ti;
        }
        __syncthreads();
    }
    float* M = (bi2 >= 4) ? g_Mk : g_Mq;
    size_t mb = (size_t)(bi2 & 3) << 19;
    for (int idx = t; idx < 4096; idx += 512) {
        int r = idx >> 2, c = idx & 3;
        M[mb + (size_t)r * 512 + j0 + c] = re[idx];
    }
}

// ---------------------------------------------------------------------------
// Multi-scale stencil, smem-staged, 4 r_o per block.
// Also zeroes the attn_out region of d_out (needed by attn's global atomics).
// ---------------------------------------------------------------------------
template <int C>
__device__ __forceinline__ float stencilS(const float* __restrict__ tile,
                                          const float* __restrict__ w,
                                          int r_o, int jp, int d2, int rr0) {
    float acc = 0.f;
#pragma unroll
    for (int ci = 0; ci < C; ci++) {
        int tt  = 64 * ci + d2;
        int il  = 9 - C + (tt % C);
        int col = jp + (tt / C) - C;
        if ((r_o - 9 + il) >= 0 && col >= 0)
            acc = fmaf(__ldg(w + ci), tile[(rr0 + il) * 513 + col], acc);
    }
    return acc;
}

__global__ void __launch_bounds__(512) multiscale(
    const float* __restrict__ wq1, const float* __restrict__ bq1,
    const float* __restrict__ wq3, const float* __restrict__ bq3,
    const float* __restrict__ wq6, const float* __restrict__ bq6,
    const float* __restrict__ wq9, const float* __restrict__ bq9,
    const float* __restrict__ wk1, const float* __restrict__ bk1,
    const float* __restrict__ wk3, const float* __restrict__ bk3,
    const float* __restrict__ wk6, const float* __restrict__ bk6,
    const float* __restrict__ wk9, const float* __restrict__ bk9,
    float* __restrict__ out) {
    __shared__ float tile[12 * 513];
    __shared__ float sbuf[4 * 64 * 9];
    int t   = threadIdx.x;
    int d2  = t & 63;
    int l2i = (t >> 6) & 7;
    int bx4 = blockIdx.x;                      // 0..31
    int bh  = blockIdx.y;
    int which = blockIdx.z;
    int b = bh >> 3, hi = bh & 7;

    if (t < 64) {
        int blk = (which * 32 + bh) * 32 + bx4;
        out[2097152 + blk * 64 + t] = 0.f;
    }

    const float* M = which ? g_Mk : g_Mq;
    float* P       = which ? g_Pk : g_Pq;
    const float* w1 = which ? wk1 : wq1;  const float* b1 = which ? bk1 : bq1;
    const float* w3 = which ? wk3 : wq3;  const float* b3 = which ? bk3 : bq3;
    const float* w6 = which ? wk6 : wq6;  const float* b6 = which ? bk6 : bq6;
    const float* w9 = which ? wk9 : wq9;  const float* b9 = which ? bk9 : bq9;
    float scale = which ? 1.0f : 0.125f;

    const float* Mb = M + ((size_t)b << 19);
    int r_o0 = (hi << 7) + bx4 * 4;
    int jp   = l2i << 6;

    for (int i = t; i < 12 * 512; i += 512) {
        int rr = i >> 9, cc = i & 511;
        int grow = r_o0 - 9 + rr;
        tile[rr * 513 + cc] = (grow >= 0) ? __ldg(Mb + grow * 512 + cc) : 0.f;
    }
    __syncthreads();

#pragma unroll
    for (int rr0 = 0; rr0 < 4; rr0++) {
        int r_o = r_o0 + rr0;
        float v0 = (__ldg(b1) + stencilS<1>(tile, w1, r_o, jp, d2, rr0)) * scale;
        float v1 = (__ldg(b3) + stencilS<3>(tile, w3, r_o, jp, d2, rr0)) * scale;
        float v2 = (__ldg(b6) + stencilS<6>(tile, w6, r_o, jp, d2, rr0)) * scale;
        float v3 = (__ldg(b9) + stencilS<9>(tile, w9, r_o, jp, d2, rr0)) * scale;

        sbuf[0 * 576 + d2 * 9 + l2i] = v0;
        sbuf[1 * 576 + d2 * 9 + l2i] = v1;
        sbuf[2 * 576 + d2 * 9 + l2i] = v2;
        sbuf[3 * 576 + d2 * 9 + l2i] = v3;
        __syncthreads();

        int l2base = (bx4 * 4 + rr0) * 8;
#pragma unroll
        for (int i = 0; i < 4; i++) {
            int idx = i * 512 + t;
            int l   = idx & 7;
            int d2s = (idx >> 3) & 63;
            int p   = idx >> 9;
            P[((size_t)(bh * 4 + p) * 64 + d2s) * 1024 + l2base + l] =
                sbuf[p * 576 + d2s * 9 + l];
        }
        if (rr0 < 3) __syncthreads();
    }
}

// ---------------------------------------------------------------------------
// Fused attention. Grid (16 kt, 32 bh, 2 qh). Block 512 = 16 warps.
// Warp w: p = w&3, q-group = w>>2 (32 q of the 128q slab).
// Thread: 8q x 8k x 1p tile -> acc = 32 ull (64 regs) -> 4 warps/SMSP.
// Softmax over p via a 128KB smem score buffer per 128q slab.
// ---------------------------------------------------------------------------
extern __shared__ char smem_raw[];
#define SM_KS 0
#define SM_QS 65536
#define SM_SC 98304
#define SM_RED 229376
#define SM_TOT 230400

__global__ void __launch_bounds__(512, 1) attn_kernel(float* __restrict__ out) {
    float* Ks = (float*)(smem_raw + SM_KS);                    // [4p][64d][64k]
    unsigned long long* Qs = (unsigned long long*)(smem_raw + SM_QS); // [4p][8dd][128q] dup
    float* Sc = (float*)(smem_raw + SM_SC);                    // [4p][128q][64k]
    float* red = (float*)(smem_raw + SM_RED);                  // [256]

    int t = threadIdx.x;
    int lane = t & 31, w = t >> 5;
    int wp = w & 3;              // warp's p
    int qq = w >> 2;             // warp's q-group (32 q)
    int kx = lane & 7;           // 8 k per thread
    int qx = lane >> 3;          // 4 q-subgroups of 8
    int k0 = kx * 8;
    int q0 = qq * 32 + qx * 8;   // within 128q slab

    int kt = blockIdx.x, bh = blockIdx.y, qh = blockIdx.z;
    const float* Pq = g_Pq + (size_t)bh * 262144;
    const float* Pk = g_Pk + (size_t)bh * 262144;

    // Stage K tile [4p][64d][64k]
#pragma unroll
    for (int i = 0; i < 8; i++) {
        int s = i * 512 + t;
        int k4 = s & 15, d = (s >> 4) & 63, p = s >> 10;
        float4 v = *(const float4*)(Pk + ((size_t)(p * 64 + d) * 1024 + kt * 64 + k4 * 4));
        *(float4*)(Ks + (p * 64 + d) * 64 + k4 * 4) = v;
    }
    if (t < 256) red[t] = 0.f;

    float alq[4][4];
#pragma unroll
    for (int p = 0; p < 4; p++)
#pragma unroll
        for (int k = 0; k < 4; k++) alq[p][k] = 0.f;

    // Prefetch chunk 0 (slab 0): [4p][8dd][128q] = 4096 floats, 8/thread
    float pre[8];
#pragma unroll
    for (int i = 0; i < 8; i++) {
        int s = i * 512 + t;
        int q = s & 127, ddl = (s >> 7) & 7, p = s >> 10;
        pre[i] = __ldg(Pq + (size_t)(p * 64 + ddl) * 1024 + qh * 512 + q);
    }

    unsigned long long acc[8][4];

    for (int sc = 0; sc < 32; sc++) {        // slab(0..3)*8 + chunk(0..7)
        int chunk = sc & 7;
        __syncthreads();                      // Qs consumed / Sc reads done
#pragma unroll
        for (int i = 0; i < 8; i++) {
            int s = i * 512 + t;
            int q = s & 127, ddl = (s >> 7) & 7, p = s >> 10;
            Qs[(p * 8 + ddl) * 128 + q] = pk2(pre[i], pre[i]);
        }
        __syncthreads();

        if (sc < 31) {
            int nslab = (sc + 1) >> 3, nchunk = (sc + 1) & 7;
#pragma unroll
            for (int i = 0; i < 8; i++) {
                int s = i * 512 + t;
                int q = s & 127, ddl = (s >> 7) & 7, p = s >> 10;
                pre[i] = __ldg(Pq + (size_t)(p * 64 + nchunk * 8 + ddl) * 1024 +
                               qh * 512 + nslab * 128 + q);
            }
        }

        if (chunk == 0) {
#pragma unroll
            for (int q = 0; q < 8; q++)
#pragma unroll
                for (int j = 0; j < 4; j++) acc[q][j] = 0ull;
        }

#pragma unroll
        for (int ddl = 0; ddl < 8; ddl++) {
            int dg = chunk * 8 + ddl;
            const ulonglong2* kvp = (const ulonglong2*)(Ks + (wp * 64 + dg) * 64 + k0);
            ulonglong2 kv0 = kvp[0];
            ulonglong2 kv1 = kvp[1];
            const unsigned long long* qr = Qs + (wp * 8 + ddl) * 128 + q0;
            ulonglong2 qA = *(const ulonglong2*)(qr);
            ulonglong2 qB = *(const ulonglong2*)(qr + 2);
            ulonglong2 qC = *(const ulonglong2*)(qr + 4);
            ulonglong2 qD = *(const ulonglong2*)(qr + 6);
            unsigned long long qv[8] = {qA.x, qA.y, qB.x, qB.y, qC.x, qC.y, qD.x, qD.y};
#pragma unroll
            for (int q = 0; q < 8; q++) {
                acc[q][0] = ffma2(qv[q], kv0.x, acc[q][0]);
                acc[q][1] = ffma2(qv[q], kv0.y, acc[q][1]);
                acc[q][2] = ffma2(qv[q], kv1.x, acc[q][2]);
                acc[q][3] = ffma2(qv[q], kv1.y, acc[q][3]);
            }
        }

        if (chunk == 7) {
            // write this slab's scores: [wp][q0+q][k0..k0+7]
#pragma unroll
            for (int q = 0; q < 8; q++) {
                ulonglong2* dst = (ulonglong2*)(Sc + ((wp * 128) + q0 + q) * 64 + k0);
                ulonglong2 v0; v0.x = acc[q][0]; v0.y = acc[q][1];
                ulonglong2 v1; v1.x = acc[q][2]; v1.y = acc[q][3];
                dst[0] = v0;
                dst[1] = v1;
            }
            __syncthreads();
            // softmax over p; each thread owns 4q x 4k cells
            int kq = t & 15, qi = t >> 4;    // kq: k-quad, qi: 32 q-rows of 4
#pragma unroll
            for (int qj = 0; qj < 4; qj++) {
                int qr2 = qi * 4 + qj;
                float4 s0 = *(const float4*)(Sc + (0 * 128 + qr2) * 64 + kq * 4);
                float4 s1 = *(const float4*)(Sc + (1 * 128 + qr2) * 64 + kq * 4);
                float4 s2 = *(const float4*)(Sc + (2 * 128 + qr2) * 64 + kq * 4);
                float4 s3 = *(const float4*)(Sc + (3 * 128 + qr2) * 64 + kq * 4);
                const float* a0 = &s0.x; const float* a1 = &s1.x;
                const float* a2 = &s2.x; const float* a3 = &s3.x;
#pragma unroll
                for (int kk = 0; kk < 4; kk++) {
                    float v0 = a0[kk], v1 = a1[kk], v2 = a2[kk], v3 = a3[kk];
                    float m = fmaxf(fmaxf(v0, v1), fmaxf(v2, v3));
                    float d0 = v0 - m, d1 = v1 - m, d2 = v2 - m, d3 = v3 - m;
                    const float TH = -87.f;
                    int cnt = (d0 > TH) + (d1 > TH) + (d2 > TH) + (d3 > TH);
                    if (cnt == 1) {
                        alq[0][kk] += (d0 == 0.f) ? 1.f : 0.f;
                        alq[1][kk] += (d1 == 0.f) ? 1.f : 0.f;
                        alq[2][kk] += (d2 == 0.f) ? 1.f : 0.f;
                        alq[3][kk] += (d3 == 0.f) ? 1.f : 0.f;
                    } else {
                        float e0 = __expf(d0), e1 = __expf(d1);
                        float e2 = __expf(d2), e3 = __expf(d3);
                        float inv = 1.f / (e0 + e1 + e2 + e3);
                        alq[0][kk] += e0 * inv; alq[1][kk] += e1 * inv;
                        alq[2][kk] += e2 * inv; alq[3][kk] += e3 * inv;
                    }
                }
            }
        }
    }

    // Reduce: smem atomics keyed by (p, k = (t&15)*4 + kk), then global atomic
    {
        int kq = t & 15;
#pragma unroll
        for (int p = 0; p < 4; p++)
#pragma unroll
            for (int kk = 0; kk < 4; kk++)
                atomicAdd(&red[p * 64 + kq * 4 + kk], alq[p][kk]);
    }
    __syncthreads();
    if (t < 256) {
        int p = t >> 6, k = t & 63;
        atomicAdd(&out[2097152 + (size_t)(bh * 4 + p) * 1024 + kt * 64 + k], red[t]);
    }
}

// ---------------------------------------------------------------------------
// context[b,h,q,d] = sum_k V[b,h,k,d]  (softmax over p sums to 1 exactly)
// ---------------------------------------------------------------------------
__global__ void context_kernel(const float* __restrict__ V, float* __restrict__ out) {
    __shared__ float part[4][64];
    __shared__ float fin[64];
    int bh = blockIdx.x;
    int t = threadIdx.x;           // 256
    int d = t & 63, pr = t >> 6;
    const float* Vb = V + (size_t)bh * 65536;
    float s = 0.f;
    for (int k = pr * 256; k < pr * 256 + 256; k++) s += Vb[(size_t)k * 64 + d];
    part[pr][d] = s;
    __syncthreads();
    if (t < 64) fin[t] = part[0][t] + part[1][t] + part[2][t] + part[3][t];
    __syncthreads();
    float* ob = out + (size_t)bh * 65536;
#pragma unroll 4
    for (int i = 0; i < 256; i++) {
        int lin = i * 256 + t;
        ob[lin] = fin[lin & 63];
    }
}

// ---------------------------------------------------------------------------
extern "C" void kernel_launch(void* const* d_in, const int* in_sizes, int n_in,
                              void* d_out, int out_size) {
    (void)in_sizes; (void)n_in; (void)out_size;
    const float* Q = (const float*)d_in[0];
    const float* K = (const float*)d_in[1];
    const float* V = (const float*)d_in[2];
    const float* wq1 = (const float*)d_in[3];  const float* bq1 = (const float*)d_in[4];
    const float* wq3 = (const float*)d_in[5];  const float* bq3 = (const float*)d_in[6];
    const float* wq6 = (const float*)d_in[7];  const float* bq6 = (const float*)d_in[8];
    const float* wq9 = (const float*)d_in[9];  const float* bq9 = (const float*)d_in[10];
    const float* wk1 = (const float*)d_in[11]; const float* bk1 = (const float*)d_in[12];
    const float* wk3 = (const float*)d_in[13]; const float* bk3 = (const float*)d_in[14];
    const float* wk6 = (const float*)d_in[15]; const float* bk6 = (const float*)d_in[16];
    const float* wk9 = (const float*)d_in[17]; const float* bk9 = (const float*)d_in[18];
    float* out = (float*)d_out;

    fft512_rows<<<8192, 256>>>(Q, K);
    fft1024_cols<<<1024, 512>>>();

    multiscale<<<dim3(32, 32, 2), 512>>>(wq1, bq1, wq3, bq3, wq6, bq6, wq9, bq9,
                                         wk1, bk1, wk3, bk3, wk6, bk6, wk9, bk9, out);

    cudaFuncSetAttribute(attn_kernel, cudaFuncAttributeMaxDynamicSharedMemorySize, SM_TOT);
    attn_kernel<<<dim3(16, 32, 2), 512, SM_TOT>>>(out);   // launch #4 -> profiled

    context_kernel<<<32, 256>>>(V, out);
}

// round 13
// speedup vs baseline: 1.0403x; 1.0403x over previous
#include <cuda_runtime.h>

// ---------------------------------------------------------------------------
// Shapes: b=4, h=8, l=1024, d=64. Per-batch flat matrix M: 1024 x 512.
// Outputs: context (4,8,1024,64) then attn_out (4,8,4,1024).
// ---------------------------------------------------------------------------

__device__ float  g_cre[2 * 4 * 1024 * 512];
__device__ float  g_cim[2 * 4 * 1024 * 512];
__device__ float  g_Mq [4 * 1024 * 512];
__device__ float  g_Mk [4 * 1024 * 512];
// P layout: [bh(32)][p(4)][d(64)][l(1024)]
__device__ float  g_Pq [32 * 4 * 64 * 1024];
__device__ float  g_Pk [32 * 4 * 64 * 1024];

// ----------------------------- f32x2 helpers -------------------------------
__device__ __forceinline__ unsigned long long pk2(float a, float b) {
    unsigned long long r;
    asm("mov.b64 %0, {%1, %2};" : "=l"(r) : "f"(a), "f"(b));
    return r;
}
__device__ __forceinline__ float2 up2(unsigned long long u) {
    float2 v;
    asm("mov.b64 {%0, %1}, %2;" : "=f"(v.x), "=f"(v.y) : "l"(u));
    return v;
}
__device__ __forceinline__ unsigned long long ffma2(unsigned long long a,
                                                    unsigned long long b,
                                                    unsigned long long c) {
    unsigned long long d;
    asm("fma.rn.f32x2 %0, %1, %2, %3;" : "=l"(d) : "l"(a), "l"(b), "l"(c));
    return d;
}

// ---------------------------------------------------------------------------
// Stage 1: 512-pt FFT along each contiguous row. Handles Q and K in one grid.
// ---------------------------------------------------------------------------
__global__ void fft512_rows(const float* __restrict__ Qin,
                            const float* __restrict__ Kin) {
    __shared__ float re[512], im[512];
    int R = blockIdx.x;                        // 0..8191
    const float* src = (R < 4096) ? Qin : Kin;
    const float* row = src + (size_t)(R & 4095) * 512;
    int t = threadIdx.x;  // 256
    for (int i = t; i < 512; i += 256) {
        re[i] = row[__brev((unsigned)i) >> 23];
        im[i] = 0.f;
    }
    __syncthreads();
    for (int s = 0; s < 9; s++) {
        int hl = 1 << s;
        int pos = t & (hl - 1);
        int i0 = ((t >> s) << (s + 1)) + pos;
        int i1 = i0 + hl;
        float si, co;
        sincospif(-(float)pos / (float)hl, &si, &co);
        float xr = re[i1], xi = im[i1];
        float tr = co * xr - si * xi;
        float ti = co * xi + si * xr;
        float ur = re[i0], ui = im[i0];
        re[i0] = ur + tr; im[i0] = ui + ti;
        re[i1] = ur - tr; im[i1] = ui - ti;
        __syncthreads();
    }
    float* cr = g_cre + (size_t)R * 512;
    float* ci = g_cim + (size_t)R * 512;
    for (int i = t; i < 512; i += 256) { cr[i] = re[i]; ci[i] = im[i]; }
}

// ---------------------------------------------------------------------------
// Stage 2: 1024-pt FFT along columns, keep real part. Handles Q and K.
// ---------------------------------------------------------------------------
__global__ void fft1024_cols() {
    __shared__ float re[4096], im[4096];
    int t = threadIdx.x;                 // 512
    int bi2 = blockIdx.x >> 7;           // 0..7 = which*4 + b
    int j0  = (blockIdx.x & 127) << 2;
    size_t gb = (size_t)bi2 << 19;
    for (int idx = t; idx < 4096; idx += 512) {
        int r = idx >> 2, c = idx & 3;
        int rv = __brev((unsigned)r) >> 22;
        size_t a = gb + (size_t)rv * 512 + j0 + c;
        re[idx] = g_cre[a];
        im[idx] = g_cim[a];
    }
    __syncthreads();
    for (int s = 0; s < 10; s++) {
        for (int u = t; u < 2048; u += 512) {
            int c = u & 3, jb = u >> 2;
            int hl = 1 << s;
            int pos = jb & (hl - 1);
            int i0 = ((jb >> s) << (s + 1)) + pos;
            int i1 = i0 + hl;
            float si, co;
            sincospif(-(float)pos / (float)hl, &si, &co);
            int a0 = (i0 << 2) + c, a1 = (i1 << 2) + c;
            float xr = re[a1], xi = im[a1];
            float tr = co * xr - si * xi;
            float ti = co * xi + si * xr;
            float ur = re[a0], ui = im[a0];
            re[a0] = ur + tr; im[a0] = ui + ti;
            re[a1] = ur - tr; im[a1] = ui - ti;
        }
        __syncthreads();
    }
    float* M = (bi2 >= 4) ? g_Mk : g_Mq;
    size_t mb = (size_t)(bi2 & 3) << 19;
    for (int idx = t; idx < 4096; idx += 512) {
        int r = idx >> 2, c = idx & 3;
        M[mb + (size_t)r * 512 + j0 + c] = re[idx];
    }
}

// ---------------------------------------------------------------------------
// Multi-scale stencil, smem-staged, 4 r_o per block.
// Also zeroes the attn_out region of d_out (needed by attn's global atomics).
// ---------------------------------------------------------------------------
template <int C>
__device__ __forceinline__ float stencilS(const float* __restrict__ tile,
                                          const float* __restrict__ w,
                                          int r_o, int jp, int d2, int rr0) {
    float acc = 0.f;
#pragma unroll
    for (int ci = 0; ci < C; ci++) {
        int tt  = 64 * ci + d2;
        int il  = 9 - C + (tt % C);
        int col = jp + (tt / C) - C;
        if ((r_o - 9 + il) >= 0 && col >= 0)
            acc = fmaf(__ldg(w + ci), tile[(rr0 + il) * 513 + col], acc);
    }
    return acc;
}

__global__ void __launch_bounds__(512) multiscale(
    const float* __restrict__ wq1, const float* __restrict__ bq1,
    const float* __restrict__ wq3, const float* __restrict__ bq3,
    const float* __restrict__ wq6, const float* __restrict__ bq6,
    const float* __restrict__ wq9, const float* __restrict__ bq9,
    const float* __restrict__ wk1, const float* __restrict__ bk1,
    const float* __restrict__ wk3, const float* __restrict__ bk3,
    const float* __restrict__ wk6, const float* __restrict__ bk6,
    const float* __restrict__ wk9, const float* __restrict__ bk9,
    float* __restrict__ out) {
    __shared__ float tile[12 * 513];          // rows r_o0-9 .. r_o0+2
    __shared__ float sbuf[4 * 64 * 9];        // output stage, padded stride 9
    int t   = threadIdx.x;
    int d2  = t & 63;
    int l2i = (t >> 6) & 7;
    int bx4 = blockIdx.x;                      // 0..31
    int bh  = blockIdx.y;
    int which = blockIdx.z;
    int b = bh >> 3, hi = bh & 7;

    // Zero attn_out region: 2048 blocks x 64 floats = 131072
    if (t < 64) {
        int blk = (which * 32 + bh) * 32 + bx4;
        out[2097152 + blk * 64 + t] = 0.f;
    }

    const float* M = which ? g_Mk : g_Mq;
    float* P       = which ? g_Pk : g_Pq;
    const float* w1 = which ? wk1 : wq1;  const float* b1 = which ? bk1 : bq1;
    const float* w3 = which ? wk3 : wq3;  const float* b3 = which ? bk3 : bq3;
    const float* w6 = which ? wk6 : wq6;  const float* b6 = which ? bk6 : bq6;
    const float* w9 = which ? wk9 : wq9;  const float* b9 = which ? bk9 : bq9;
    float scale = which ? 1.0f : 0.125f;

    const float* Mb = M + ((size_t)b << 19);
    int r_o0 = (hi << 7) + bx4 * 4;
    int jp   = l2i << 6;

    // Stage 12 support rows (coalesced)
    for (int i = t; i < 12 * 512; i += 512) {
        int rr = i >> 9, cc = i & 511;
        int grow = r_o0 - 9 + rr;
        tile[rr * 513 + cc] = (grow >= 0) ? __ldg(Mb + grow * 512 + cc) : 0.f;
    }
    __syncthreads();

#pragma unroll
    for (int rr0 = 0; rr0 < 4; rr0++) {
        int r_o = r_o0 + rr0;
        float v0 = (__ldg(b1) + stencilS<1>(tile, w1, r_o, jp, d2, rr0)) * scale;
        float v1 = (__ldg(b3) + stencilS<3>(tile, w3, r_o, jp, d2, rr0)) * scale;
        float v2 = (__ldg(b6) + stencilS<6>(tile, w6, r_o, jp, d2, rr0)) * scale;
        float v3 = (__ldg(b9) + stencilS<9>(tile, w9, r_o, jp, d2, rr0)) * scale;

        sbuf[0 * 576 + d2 * 9 + l2i] = v0;
        sbuf[1 * 576 + d2 * 9 + l2i] = v1;
        sbuf[2 * 576 + d2 * 9 + l2i] = v2;
        sbuf[3 * 576 + d2 * 9 + l2i] = v3;
        __syncthreads();

        int l2base = (bx4 * 4 + rr0) * 8;
#pragma unroll
        for (int i = 0; i < 4; i++) {
            int idx = i * 512 + t;
            int l   = idx & 7;
            int d2s = (idx >> 3) & 63;
            int p   = idx >> 9;
            P[((size_t)(bh * 4 + p) * 64 + d2s) * 1024 + l2base + l] =
                sbuf[p * 576 + d2s * 9 + l];
        }
        if (rr0 < 3) __syncthreads();
    }
}

// ---------------------------------------------------------------------------
// Fused attention, barrier-free mainloop. Grid (16 kt, 32 bh, 2 qh).
// Block 256 = 16 tx (4k) x 16 ty (8q). Per qt slab (128q): acc[4p][4qpair][4k].
// K staged once in smem (non-dup; dup'd to f32x2 in regs via pk2).
// Q pairs loaded straight from global as ulonglong2 (L1-resident, no STS/BAR).
// ---------------------------------------------------------------------------
__device__ __forceinline__ void smax4(float a0, float a1, float a2, float a3,
                                      float (&al)[4][4], int kk) {
    float m  = fmaxf(fmaxf(a0, a1), fmaxf(a2, a3));
    float d0 = a0 - m, d1 = a1 - m, d2 = a2 - m, d3 = a3 - m;
    const float TH = -87.f;
    int cnt = (d0 > TH) + (d1 > TH) + (d2 > TH) + (d3 > TH);
    if (cnt == 1) {   // one-hot (reference exp underflows to exactly this)
        al[0][kk] += (d0 == 0.f) ? 1.f : 0.f;
        al[1][kk] += (d1 == 0.f) ? 1.f : 0.f;
        al[2][kk] += (d2 == 0.f) ? 1.f : 0.f;
        al[3][kk] += (d3 == 0.f) ? 1.f : 0.f;
    } else {
        float e0 = __expf(d0), e1 = __expf(d1), e2 = __expf(d2), e3 = __expf(d3);
        float inv = 1.f / (e0 + e1 + e2 + e3);
        al[0][kk] += e0 * inv; al[1][kk] += e1 * inv;
        al[2][kk] += e2 * inv; al[3][kk] += e3 * inv;
    }
}

extern __shared__ char smem_raw[];

__global__ void __launch_bounds__(256, 1) attn_kernel(float* __restrict__ out) {
    // smem: Ks float[4][64][64] (64KB) | red float[256]
    float* Ks = (float*)smem_raw;
    float* red = (float*)(smem_raw + 65536);

    int t  = threadIdx.x;
    int tx = t & 15, ty = t >> 4;
    int kt = blockIdx.x, bh = blockIdx.y;
    int qh = blockIdx.z;
    const float* Pq = g_Pq + (size_t)bh * 262144;
    const float* Pk = g_Pk + (size_t)bh * 262144;

    // Stage K tile [p][d(64)][k(64)] once
#pragma unroll
    for (int i = 0; i < 16; i++) {
        int s = i * 256 + t;               // 4096 float4 slots
        int k4 = s & 15, d = (s >> 4) & 63, p = s >> 10;
        float4 v = *(const float4*)(Pk + ((size_t)(p * 64 + d) * 1024 + kt * 64 + k4 * 4));
        *(float4*)(Ks + (p * 64 + d) * 64 + k4 * 4) = v;
    }
    red[t] = 0.f;
    __syncthreads();    // the ONLY barrier before the epilogue

    float al[4][4];
#pragma unroll
    for (int p = 0; p < 4; p++)
#pragma unroll
        for (int k = 0; k < 4; k++) al[p][k] = 0.f;

    // q base for this thread: 8 consecutive q = 4 natural f32x2 pairs
    const size_t qbase = (size_t)qh * 512 + ty * 8;

    for (int qt = 0; qt < 4; qt++) {       // 4 slabs of 128 q
        unsigned long long acc[4][4][4];   // [p][qpair][k]
#pragma unroll
        for (int p = 0; p < 4; p++)
#pragma unroll
            for (int q = 0; q < 4; q++)
#pragma unroll
                for (int k = 0; k < 4; k++) acc[p][q][k] = 0ull;

#pragma unroll 4
        for (int dd = 0; dd < 64; dd++) {
#pragma unroll
            for (int p = 0; p < 4; p++) {
                // K: 4 floats from smem, dup'd to f32x2 in regs
                float4 kf = *(const float4*)(Ks + (p * 64 + dd) * 64 + tx * 4);
                unsigned long long k0 = pk2(kf.x, kf.x);
                unsigned long long k1 = pk2(kf.y, kf.y);
                unsigned long long k2 = pk2(kf.z, kf.z);
                unsigned long long k3 = pk2(kf.w, kf.w);
                // Q: 4 natural pairs straight from global (L1 hit)
                const ulonglong2* qp = (const ulonglong2*)
                    (Pq + (size_t)(p * 64 + dd) * 1024 + qbase + qt * 128);
                ulonglong2 qa = __ldg(qp);
                ulonglong2 qb = __ldg(qp + 1);
#pragma unroll
                for (int k = 0; k < 4; k++) {
                    unsigned long long kv = (k == 0) ? k0 : (k == 1) ? k1
                                          : (k == 2) ? k2 : k3;
                    acc[p][0][k] = ffma2(qa.x, kv, acc[p][0][k]);
                    acc[p][1][k] = ffma2(qa.y, kv, acc[p][1][k]);
                    acc[p][2][k] = ffma2(qb.x, kv, acc[p][2][k]);
                    acc[p][3][k] = ffma2(qb.y, kv, acc[p][3][k]);
                }
            }
        }

        // softmax over p for 8q x 4k, accumulate per-k sums
#pragma unroll
        for (int q = 0; q < 4; q++) {
#pragma unroll
            for (int k = 0; k < 4; k++) {
                float2 v0 = up2(acc[0][q][k]);
                float2 v1 = up2(acc[1][q][k]);
                float2 v2 = up2(acc[2][q][k]);
                float2 v3 = up2(acc[3][q][k]);
                smax4(v0.x, v1.x, v2.x, v3.x, al, k);
                smax4(v0.y, v1.y, v2.y, v3.y, al, k);
            }
        }
    }

    // Reduce via smem atomics, then one global atomicAdd per cell (2-way: qh)
#pragma unroll
    for (int p = 0; p < 4; p++)
#pragma unroll
        for (int kk = 0; kk < 4; kk++)
            atomicAdd(&red[p * 64 + tx * 4 + kk], al[p][kk]);
    __syncthreads();
    {
        int p = t >> 6, k = t & 63;
        atomicAdd(&out[2097152 + (size_t)(bh * 4 + p) * 1024 + kt * 64 + k], red[t]);
    }
}

// ---------------------------------------------------------------------------
// context[b,h,q,d] = sum_k V[b,h,k,d]  (softmax over p sums to 1 exactly)
// ---------------------------------------------------------------------------
__global__ void context_kernel(const float* __restrict__ V, float* __restrict__ out) {
    __shared__ float part[4][64];
    __shared__ float fin[64];
    int bh = blockIdx.x;
    int t = threadIdx.x;           // 256
    int d = t & 63, pr = t >> 6;
    const float* Vb = V + (size_t)bh * 65536;
    float s = 0.f;
    for (int k = pr * 256; k < pr * 256 + 256; k++) s += Vb[(size_t)k * 64 + d];
    part[pr][d] = s;
    __syncthreads();
    if (t < 64) fin[t] = part[0][t] + part[1][t] + part[2][t] + part[3][t];
    __syncthreads();
    float* ob = out + (size_t)bh * 65536;
#pragma unroll 4
    for (int i = 0; i < 256; i++) {
        int lin = i * 256 + t;
        ob[lin] = fin[lin & 63];
    }
}

// ---------------------------------------------------------------------------
extern "C" void kernel_launch(void* const* d_in, const int* in_sizes, int n_in,
                              void* d_out, int out_size) {
    (void)in_sizes; (void)n_in; (void)out_size;
    const float* Q = (const float*)d_in[0];
    const float* K = (const float*)d_in[1];
    const float* V = (const float*)d_in[2];
    const float* wq1 = (const float*)d_in[3];  const float* bq1 = (const float*)d_in[4];
    const float* wq3 = (const float*)d_in[5];  const float* bq3 = (const float*)d_in[6];
    const float* wq6 = (const float*)d_in[7];  const float* bq6 = (const float*)d_in[8];
    const float* wq9 = (const float*)d_in[9];  const float* bq9 = (const float*)d_in[10];
    const float* wk1 = (const float*)d_in[11]; const float* bk1 = (const float*)d_in[12];
    const float* wk3 = (const float*)d_in[13]; const float* bk3 = (const float*)d_in[14];
    const float* wk6 = (const float*)d_in[15]; const float* bk6 = (const float*)d_in[16];
    const float* wk9 = (const float*)d_in[17]; const float* bk9 = (const float*)d_in[18];
    float* out = (float*)d_out;

    fft512_rows<<<8192, 256>>>(Q, K);
    fft1024_cols<<<1024, 512>>>();

    multiscale<<<dim3(32, 32, 2), 512>>>(wq1, bq1, wq3, bq3, wq6, bq6, wq9, bq9,
                                         wk1, bk1, wk3, bk3, wk6, bk6, wk9, bk9, out);

    cudaFuncSetAttribute(attn_kernel, cudaFuncAttributeMaxDynamicSharedMemorySize, 66560);
    attn_kernel<<<dim3(16, 32, 2), 256, 66560>>>(out);   // launch #4 -> profiled

    context_kernel<<<32, 256>>>(V, out);
}

// round 14
// speedup vs baseline: 1.1474x; 1.1030x over previous
#include <cuda_runtime.h>

// ---------------------------------------------------------------------------
// Shapes: b=4, h=8, l=1024, d=64. Per-batch flat matrix M: 1024 x 512.
// Outputs: context (4,8,1024,64) then attn_out (4,8,4,1024).
// ---------------------------------------------------------------------------

__device__ float  g_cre[2 * 4 * 1024 * 512];
__device__ float  g_cim[2 * 4 * 1024 * 512];
__device__ float  g_Mq [4 * 1024 * 512];
__device__ float  g_Mk [4 * 1024 * 512];
// P layout: [bh(32)][p(4)][d(64)][l(1024)]
__device__ float  g_Pq [32 * 4 * 64 * 1024];
__device__ float  g_Pk [32 * 4 * 64 * 1024];

// ----------------------------- f32x2 helpers -------------------------------
__device__ __forceinline__ unsigned long long pk2(float a, float b) {
    unsigned long long r;
    asm("mov.b64 %0, {%1, %2};" : "=l"(r) : "f"(a), "f"(b));
    return r;
}
__device__ __forceinline__ float2 up2(unsigned long long u) {
    float2 v;
    asm("mov.b64 {%0, %1}, %2;" : "=f"(v.x), "=f"(v.y) : "l"(u));
    return v;
}
__device__ __forceinline__ unsigned long long ffma2(unsigned long long a,
                                                    unsigned long long b,
                                                    unsigned long long c) {
    unsigned long long d;
    asm("fma.rn.f32x2 %0, %1, %2, %3;" : "=l"(d) : "l"(a), "l"(b), "l"(c));
    return d;
}

// ---------------------------------------------------------------------------
// Stage 1: 512-pt FFT along each contiguous row. Handles Q and K in one grid.
// Twiddles from a per-block smem LUT: tw[j] = exp(-i*pi*j/512); butterfly at
// stage s uses j = pos << (9-s).  (Kills ~2300 sincospif/block of MUFU work.)
// ---------------------------------------------------------------------------
__global__ void fft512_rows(const float* __restrict__ Qin,
                            const float* __restrict__ Kin) {
    __shared__ float re[512], im[512];
    __shared__ float2 tw[512];
    int R = blockIdx.x;                        // 0..8191
    const float* src = (R < 4096) ? Qin : Kin;
    const float* row = src + (size_t)(R & 4095) * 512;
    int t = threadIdx.x;  // 256
    for (int i = t; i < 512; i += 256) {
        re[i] = row[__brev((unsigned)i) >> 23];
        im[i] = 0.f;
        float si, co;
        sincospif(-(float)i / 512.f, &si, &co);
        tw[i] = make_float2(co, si);
    }
    __syncthreads();
    for (int s = 0; s < 9; s++) {
        int hl = 1 << s;
        int pos = t & (hl - 1);
        int i0 = ((t >> s) << (s + 1)) + pos;
        int i1 = i0 + hl;
        float2 w = tw[pos << (9 - s)];
        float xr = re[i1], xi = im[i1];
        float tr = w.x * xr - w.y * xi;
        float ti = w.x * xi + w.y * xr;
        float ur = re[i0], ui = im[i0];
        re[i0] = ur + tr; im[i0] = ui + ti;
        re[i1] = ur - tr; im[i1] = ui - ti;
        __syncthreads();
    }
    float* cr = g_cre + (size_t)R * 512;
    float* ci = g_cim + (size_t)R * 512;
    for (int i = t; i < 512; i += 256) { cr[i] = re[i]; ci[i] = im[i]; }
}

// ---------------------------------------------------------------------------
// Stage 2: 1024-pt FFT along columns, keep real part. Handles Q and K.
// Same smem twiddle LUT (stage s: j = pos << (9-s), s=0..9).
// ---------------------------------------------------------------------------
__global__ void fft1024_cols() {
    __shared__ float re[4096], im[4096];
    __shared__ float2 tw[512];
    int t = threadIdx.x;                 // 512
    int bi2 = blockIdx.x >> 7;           // 0..7 = which*4 + b
    int j0  = (blockIdx.x & 127) << 2;
    size_t gb = (size_t)bi2 << 19;
    {
        float si, co;
        sincospif(-(float)t / 512.f, &si, &co);
        tw[t] = make_float2(co, si);
    }
    for (int idx = t; idx < 4096; idx += 512) {
        int r = idx >> 2, c = idx & 3;
        int rv = __brev((unsigned)r) >> 22;
        size_t a = gb + (size_t)rv * 512 + j0 + c;
        re[idx] = g_cre[a];
        im[idx] = g_cim[a];
    }
    __syncthreads();
    for (int s = 0; s < 10; s++) {
        for (int u = t; u < 2048; u += 512) {
            int c = u & 3, jb = u >> 2;
            int hl = 1 << s;
            int pos = jb & (hl - 1);
            int i0 = ((jb >> s) << (s + 1)) + pos;
            int i1 = i0 + hl;
            float2 w = tw[pos << (9 - s)];
            int a0 = (i0 << 2) + c, a1 = (i1 << 2) + c;
            float xr = re[a1], xi = im[a1];
            float tr = w.x * xr - w.y * xi;
            float ti = w.x * xi + w.y * xr;
            float ur = re[a0], ui = im[a0];
            re[a0] = ur + tr; im[a0] = ui + ti;
            re[a1] = ur - tr; im[a1] = ui - ti;
        }
        __syncthreads();
    }
    float* M = (bi2 >= 4) ? g_Mk : g_Mq;
    size_t mb = (size_t)(bi2 & 3) << 19;
    for (int idx = t; idx < 4096; idx += 512) {
        int r = idx >> 2, c = idx & 3;
        M[mb + (size_t)r * 512 + j0 + c] = re[idx];
    }
}

// ---------------------------------------------------------------------------
// Multi-scale stencil, smem-staged, 4 r_o per block.
// Also zeroes the attn_out region of d_out (needed by attn's global atomics).
// ---------------------------------------------------------------------------
template <int C>
__device__ __forceinline__ float stencilS(const float* __restrict__ tile,
                                          const float* __restrict__ w,
                                          int r_o, int jp, int d2, int rr0) {
    float acc = 0.f;
#pragma unroll
    for (int ci = 0; ci < C; ci++) {
        int tt  = 64 * ci + d2;
        int il  = 9 - C + (tt % C);
        int col = jp + (tt / C) - C;
        if ((r_o - 9 + il) >= 0 && col >= 0)
            acc = fmaf(__ldg(w + ci), tile[(rr0 + il) * 513 + col], acc);
    }
    return acc;
}

__global__ void __launch_bounds__(512) multiscale(
    const float* __restrict__ wq1, const float* __restrict__ bq1,
    const float* __restrict__ wq3, const float* __restrict__ bq3,
    const float* __restrict__ wq6, const float* __restrict__ bq6,
    const float* __restrict__ wq9, const float* __restrict__ bq9,
    const float* __restrict__ wk1, const float* __restrict__ bk1,
    const float* __restrict__ wk3, const float* __restrict__ bk3,
    const float* __restrict__ wk6, const float* __restrict__ bk6,
    const float* __restrict__ wk9, const float* __restrict__ bk9,
    float* __restrict__ out) {
    __shared__ float tile[12 * 513];          // rows r_o0-9 .. r_o0+2
    __shared__ float sbuf[4 * 64 * 9];        // output stage, padded stride 9
    int t   = threadIdx.x;
    int d2  = t & 63;
    int l2i = (t >> 6) & 7;
    int bx4 = blockIdx.x;                      // 0..31
    int bh  = blockIdx.y;
    int which = blockIdx.z;
    int b = bh >> 3, hi = bh & 7;

    // Zero attn_out region: 2048 blocks x 64 floats = 131072
    if (t < 64) {
        int blk = (which * 32 + bh) * 32 + bx4;
        out[2097152 + blk * 64 + t] = 0.f;
    }

    const float* M = which ? g_Mk : g_Mq;
    float* P       = which ? g_Pk : g_Pq;
    const float* w1 = which ? wk1 : wq1;  const float* b1 = which ? bk1 : bq1;
    const float* w3 = which ? wk3 : wq3;  const float* b3 = which ? bk3 : bq3;
    const float* w6 = which ? wk6 : wq6;  const float* b6 = which ? bk6 : bq6;
    const float* w9 = which ? wk9 : wq9;  const float* b9 = which ? bk9 : bq9;
    float scale = which ? 1.0f : 0.125f;

    const float* Mb = M + ((size_t)b << 19);
    int r_o0 = (hi << 7) + bx4 * 4;
    int jp   = l2i << 6;

    // Stage 12 support rows (coalesced)
    for (int i = t; i < 12 * 512; i += 512) {
        int rr = i >> 9, cc = i & 511;
        int grow = r_o0 - 9 + rr;
        tile[rr * 513 + cc] = (grow >= 0) ? __ldg(Mb + grow * 512 + cc) : 0.f;
    }
    __syncthreads();

#pragma unroll
    for (int rr0 = 0; rr0 < 4; rr0++) {
        int r_o = r_o0 + rr0;
        float v0 = (__ldg(b1) + stencilS<1>(tile, w1, r_o, jp, d2, rr0)) * scale;
        float v1 = (__ldg(b3) + stencilS<3>(tile, w3, r_o, jp, d2, rr0)) * scale;
        float v2 = (__ldg(b6) + stencilS<6>(tile, w6, r_o, jp, d2, rr0)) * scale;
        float v3 = (__ldg(b9) + stencilS<9>(tile, w9, r_o, jp, d2, rr0)) * scale;

        sbuf[0 * 576 + d2 * 9 + l2i] = v0;
        sbuf[1 * 576 + d2 * 9 + l2i] = v1;
        sbuf[2 * 576 + d2 * 9 + l2i] = v2;
        sbuf[3 * 576 + d2 * 9 + l2i] = v3;
        __syncthreads();

        int l2base = (bx4 * 4 + rr0) * 8;
#pragma unroll
        for (int i = 0; i < 4; i++) {
            int idx = i * 512 + t;
            int l   = idx & 7;
            int d2s = (idx >> 3) & 63;
            int p   = idx >> 9;
            P[((size_t)(bh * 4 + p) * 64 + d2s) * 1024 + l2base + l] =
                sbuf[p * 576 + d2s * 9 + l];
        }
        if (rr0 < 3) __syncthreads();
    }
}

// ---------------------------------------------------------------------------
// Fused attention — EXACT R8 configuration (best measured: 566us).
// Grid (16 kt, 32 bh, 2 qh). Block 256. 8q x 4k x 4p register tile, FFMA2.
// Q staging software-pipelined through registers + smem; 2-way deterministic
// global atomics over the qh halves.
// ---------------------------------------------------------------------------
__device__ __forceinline__ void smax4(float a0, float a1, float a2, float a3,
                                      float (&al)[4][4], int kk) {
    float m  = fmaxf(fmaxf(a0, a1), fmaxf(a2, a3));
    float d0 = a0 - m, d1 = a1 - m, d2 = a2 - m, d3 = a3 - m;
    const float TH = -87.f;
    int cnt = (d0 > TH) + (d1 > TH) + (d2 > TH) + (d3 > TH);
    if (cnt == 1) {   // one-hot (reference exp underflows to exactly this)
        al[0][kk] += (d0 == 0.f) ? 1.f : 0.f;
        al[1][kk] += (d1 == 0.f) ? 1.f : 0.f;
        al[2][kk] += (d2 == 0.f) ? 1.f : 0.f;
        al[3][kk] += (d3 == 0.f) ? 1.f : 0.f;
    } else {
        float e0 = __expf(d0), e1 = __expf(d1), e2 = __expf(d2), e3 = __expf(d3);
        float inv = 1.f / (e0 + e1 + e2 + e3);
        al[0][kk] += e0 * inv; al[1][kk] += e1 * inv;
        al[2][kk] += e2 * inv; al[3][kk] += e3 * inv;
    }
}

extern __shared__ char smem_raw[];

__global__ void __launch_bounds__(256, 1) attn_kernel(float* __restrict__ out) {
    // smem: Ks float[4][64][64] (64KB) | Qs ull[4][16][128] (64KB) | red float[256]
    float* Ks = (float*)smem_raw;
    unsigned long long* Qs = (unsigned long long*)(smem_raw + 65536);
    float* red = (float*)(smem_raw + 131072);

    int t  = threadIdx.x;
    int tx = t & 15, ty = t >> 4;
    int kt = blockIdx.x, bh = blockIdx.y;
    int qh = blockIdx.z;                   // q half: 0 or 1
    const float* Pq = g_Pq + (size_t)bh * 262144;
    const float* Pk = g_Pk + (size_t)bh * 262144;

    // Load full K tile [p][d(64)][k(64)]
#pragma unroll
    for (int i = 0; i < 16; i++) {
        int s = i * 256 + t;               // 4096 float4 slots
        int k4 = s & 15, d = (s >> 4) & 63, p = s >> 10;
        float4 v = *(const float4*)(Pk + ((size_t)(p * 64 + d) * 1024 + kt * 64 + k4 * 4));
        *(float4*)(Ks + (p * 64 + d) * 64 + k4 * 4) = v;
    }
    red[t] = 0.f;

    float al[4][4];
#pragma unroll
    for (int p = 0; p < 4; p++)
#pragma unroll
        for (int k = 0; k < 4; k++) al[p][k] = 0.f;

    // Prefetch chunk 0 into registers (qt = qh*4, dc = 0)
    float pre[32];
#pragma unroll
    for (int i = 0; i < 32; i++) {
        int s = i * 256 + t;
        int q = s & 127, dd = (s >> 7) & 15, p = s >> 11;
        pre[i] = __ldg(Pq + (size_t)(p * 64 + dd) * 1024 + (qh * 4) * 128 + q);
    }

    unsigned long long acc[4][8][2];

    for (int qd = 0; qd < 16; qd++) {      // qd = (qt-local)*4 + dc
        int dc = qd & 3;
        __syncthreads();                    // prior compute done reading Qs / K ready
#pragma unroll
        for (int i = 0; i < 32; i++) {
            int s = i * 256 + t;
            int q = s & 127, dd = (s >> 7) & 15, p = s >> 11;
            Qs[(p * 16 + dd) * 128 + q] = pk2(pre[i], pre[i]);
        }
        __syncthreads();

        // Prefetch next chunk (hidden behind compute below)
        if (qd < 15) {
            int nqt = qh * 4 + ((qd + 1) >> 2), ndc = (qd + 1) & 3;
#pragma unroll
            for (int i = 0; i < 32; i++) {
                int s = i * 256 + t;
                int q = s & 127, dd = (s >> 7) & 15, p = s >> 11;
                pre[i] = __ldg(Pq + (size_t)(p * 64 + ndc * 16 + dd) * 1024 + nqt * 128 + q);
            }
        }

        if (dc == 0) {
#pragma unroll
            for (int p = 0; p < 4; p++)
#pragma unroll
                for (int q = 0; q < 8; q++) { acc[p][q][0] = 0ull; acc[p][q][1] = 0ull; }
        }

#pragma unroll
        for (int dd = 0; dd < 16; dd++) {
#pragma unroll
            for (int p = 0; p < 4; p++) {
                ulonglong2 kv = *(const ulonglong2*)(Ks + (p * 64 + dc * 16 + dd) * 64 + tx * 4);
                const unsigned long long* qrow = Qs + (p * 16 + dd) * 128 + ty * 8;
                ulonglong2 qa = *(const ulonglong2*)(qrow);
                ulonglong2 qb = *(const ulonglong2*)(qrow + 2);
                ulonglong2 qc = *(const ulonglong2*)(qrow + 4);
                ulonglong2 qd2 = *(const ulonglong2*)(qrow + 6);
                acc[p][0][0] = ffma2(qa.x, kv.x, acc[p][0][0]);
                acc[p][0][1] = ffma2(qa.x, kv.y, acc[p][0][1]);
                acc[p][1][0] = ffma2(qa.y, kv.x, acc[p][1][0]);
                acc[p][1][1] = ffma2(qa.y, kv.y, acc[p][1][1]);
                acc[p][2][0] = ffma2(qb.x, kv.x, acc[p][2][0]);
                acc[p][2][1] = ffma2(qb.x, kv.y, acc[p][2][1]);
                acc[p][3][0] = ffma2(qb.y, kv.x, acc[p][3][0]);
                acc[p][3][1] = ffma2(qb.y, kv.y, acc[p][3][1]);
                acc[p][4][0] = ffma2(qc.x, kv.x, acc[p][4][0]);
                acc[p][4][1] = ffma2(qc.x, kv.y, acc[p][4][1]);
                acc[p][5][0] = ffma2(qc.y, kv.x, acc[p][5][0]);
                acc[p][5][1] = ffma2(qc.y, kv.y, acc[p][5][1]);
                acc[p][6][0] = ffma2(qd2.x, kv.x, acc[p][6][0]);
                acc[p][6][1] = ffma2(qd2.x, kv.y, acc[p][6][1]);
                acc[p][7][0] = ffma2(qd2.y, kv.x, acc[p][7][0]);
                acc[p][7][1] = ffma2(qd2.y, kv.y, acc[p][7][1]);
            }
        }

        if (dc == 3) {
            // softmax over p for the 8q x 4k micro-tile, accumulate per-k sums
#pragma unroll
            for (int q = 0; q < 8; q++) {
#pragma unroll
                for (int half = 0; half < 2; half++) {
                    float2 v0 = up2(acc[0][q][half]);
                    float2 v1 = up2(acc[1][q][half]);
                    float2 v2 = up2(acc[2][q][half]);
                    float2 v3 = up2(acc[3][q][half]);
                    smax4(v0.x, v1.x, v2.x, v3.x, al, half * 2 + 0);
                    smax4(v0.y, v1.y, v2.y, v3.y, al, half * 2 + 1);
                }
            }
        }
    }

    // Reduce over ty via smem atomics, then one global atomicAdd per cell
#pragma unroll
    for (int p = 0; p < 4; p++)
#pragma unroll
        for (int kk = 0; kk < 4; kk++)
            atomicAdd(&red[p * 64 + tx * 4 + kk], al[p][kk]);
    __syncthreads();
    {
        int p = t >> 6, k = t & 63;
        atomicAdd(&out[2097152 + (size_t)(bh * 4 + p) * 1024 + kt * 64 + k], red[t]);
    }
}

// ---------------------------------------------------------------------------
// context[b,h,q,d] = sum_k V[b,h,k,d]  (softmax over p sums to 1 exactly)
// ---------------------------------------------------------------------------
__global__ void context_kernel(const float* __restrict__ V, float* __restrict__ out) {
    __shared__ float part[4][64];
    __shared__ float fin[64];
    int bh = blockIdx.x;
    int t = threadIdx.x;           // 256
    int d = t & 63, pr = t >> 6;
    const float* Vb = V + (size_t)bh * 65536;
    float s = 0.f;
    for (int k = pr * 256; k < pr * 256 + 256; k++) s += Vb[(size_t)k * 64 + d];
    part[pr][d] = s;
    __syncthreads();
    if (t < 64) fin[t] = part[0][t] + part[1][t] + part[2][t] + part[3][t];
    __syncthreads();
    float* ob = out + (size_t)bh * 65536;
#pragma unroll 4
    for (int i = 0; i < 256; i++) {
        int lin = i * 256 + t;
        ob[lin] = fin[lin & 63];
    }
}

// ---------------------------------------------------------------------------
extern "C" void kernel_launch(void* const* d_in, const int* in_sizes, int n_in,
                              void* d_out, int out_size) {
    (void)in_sizes; (void)n_in; (void)out_size;
    const float* Q = (const float*)d_in[0];
    const float* K = (const float*)d_in[1];
    const float* V = (const float*)d_in[2];
    const float* wq1 = (const float*)d_in[3];  const float* bq1 = (const float*)d_in[4];
    const float* wq3 = (const float*)d_in[5];  const float* bq3 = (const float*)d_in[6];
    const float* wq6 = (const float*)d_in[7];  const float* bq6 = (const float*)d_in[8];
    const float* wq9 = (const float*)d_in[9];  const float* bq9 = (const float*)d_in[10];
    const float* wk1 = (const float*)d_in[11]; const float* bk1 = (const float*)d_in[12];
    const float* wk3 = (const float*)d_in[13]; const float* bk3 = (const float*)d_in[14];
    const float* wk6 = (const float*)d_in[15]; const float* bk6 = (const float*)d_in[16];
    const float* wk9 = (const float*)d_in[17]; const float* bk9 = (const float*)d_in[18];
    float* out = (float*)d_out;

    fft512_rows<<<8192, 256>>>(Q, K);
    fft1024_cols<<<1024, 512>>>();

    multiscale<<<dim3(32, 32, 2), 512>>>(wq1, bq1, wq3, bq3, wq6, bq6, wq9, bq9,
                                         wk1, bk1, wk3, bk3, wk6, bk6, wk9, bk9, out);

    cudaFuncSetAttribute(attn_kernel, cudaFuncAttributeMaxDynamicSharedMemorySize, 132096);
    attn_kernel<<<dim3(16, 32, 2), 256, 132096>>>(out);   // launch #4 -> profiled

    context_kernel<<<32, 256>>>(V, out);
}